// round 16
// baseline (speedup 1.0000x reference)
#include <cuda_runtime.h>
#include <cuda_fp16.h>
#include <math.h>
#include <stdint.h>

#define NNODES 50000
#define NFEAT  512
#define HHC    512
#define NHEAD  8
#define NCLS   16
#define NEG    0.2f
#define MAXEN  850000
#define DEGCAP 256

// GEMM1 smem staging: 2 regions (A, B) x 128 rows x 48B pitch
#define ROWS_B    48
#define REGION    (128 * ROWS_B)     // 6144
#define OFF_B     REGION
#define STG_BYTES (2 * REGION)       // 12288 per stage
#define NSTAGE    4
#define DSMEM_G1  (NSTAGE * STG_BYTES)  // 49152

// ---------------- scratch ----------------
__device__ __half g_h1h  [(size_t)NNODES * HHC];  // layer1 features, fp16
__device__ __half g_hactH[(size_t)NNODES * HHC];  // elu(emb), fp16
__device__ float g_h2  [(size_t)NNODES * NCLS];
__device__ __half g_xf [(size_t)NNODES * NFEAT];  // x, fp16
__device__ __half g_wtf[NFEAT * HHC];             // W1^T, fp16 [n][k]
__device__ float g_as1[NNODES * NHEAD];
__device__ float g_ad1[NNODES * NHEAD];
__device__ float g_as2[NNODES];
__device__ float g_ad2[NNODES];
__device__ float g_ex1[(size_t)MAXEN * NHEAD];  // fallback for deg > DEGCAP
__device__ float g_ex2[MAXEN];
__device__ int   g_src[MAXEN];
__device__ int   g_dst[MAXEN];
__device__ int   g_csrc[MAXEN];
__device__ int   g_row[NNODES + 1];
__device__ int   g_deg[NNODES];
__device__ int   g_fill[NNODES];
__device__ int   g_is64;

// ---------------- helpers ----------------
__device__ __forceinline__ uint32_t smem_u32(const void* p) {
    uint32_t a;
    asm("{ .reg .u64 t; cvta.to.shared.u64 t, %1; cvt.u32.u64 %0, t; }" : "=r"(a) : "l"(p));
    return a;
}
__device__ __forceinline__ void ldsm4(uint32_t addr, uint32_t* r) {
    asm volatile("ldmatrix.sync.aligned.m8n8.x4.shared.b16 {%0,%1,%2,%3}, [%4];"
                 : "=r"(r[0]), "=r"(r[1]), "=r"(r[2]), "=r"(r[3]) : "r"(addr));
}
#define MMA_F16(c, a, b0, b1) \
    asm volatile("mma.sync.aligned.m16n8k16.row.col.f32.f16.f16.f32 " \
        "{%0,%1,%2,%3}, {%4,%5,%6,%7}, {%8,%9}, {%0,%1,%2,%3};" \
        : "+f"((c)[0]), "+f"((c)[1]), "+f"((c)[2]), "+f"((c)[3]) \
        : "r"((a)[0]), "r"((a)[1]), "r"((a)[2]), "r"((a)[3]), "r"(b0), "r"(b1))

#define CP16(dst, src, sz) \
    asm volatile("cp.async.cg.shared.global [%0], [%1], 16, %2;" \
                 :: "r"(dst), "l"(src), "r"(sz) : "memory")
#define CP_COMMIT() asm volatile("cp.async.commit_group;" ::: "memory")
#define CP_WAIT2()  asm volatile("cp.async.wait_group 2;" ::: "memory")

// ---------------- convert x -> fp16 (+ zero alpha accumulators) --------------
__global__ void k_cvt_x(const float* __restrict__ x, size_t n4, int M) {
    size_t i = (size_t)blockIdx.x * blockDim.x + threadIdx.x;
    if (i < (size_t)M * NHEAD) { g_as1[i] = 0.f; g_ad1[i] = 0.f; }
    if (i >= n4) return;
    float4 v = ((const float4*)x)[i];
    uint2 out;
    *(__half2*)&out.x = __floats2half2_rn(v.x, v.y);
    *(__half2*)&out.y = __floats2half2_rn(v.z, v.w);
    ((uint2*)g_xf)[i] = out;
}

// ---------------- W1 transpose + convert ----------------
__global__ void k_cvt_wt(const float* __restrict__ w1) {
    __shared__ float t[32][33];
    int bx = blockIdx.x * 32, by = blockIdx.y * 32;
#pragma unroll
    for (int j = 0; j < 32; j += 8)
        t[threadIdx.y + j][threadIdx.x] = w1[(size_t)(by + threadIdx.y + j) * HHC + bx + threadIdx.x];
    __syncthreads();
#pragma unroll
    for (int j = 0; j < 32; j += 8) {
        float v = t[threadIdx.x][threadIdx.y + j];
        g_wtf[(size_t)(bx + threadIdx.y + j) * NFEAT + by + threadIdx.x] = __float2half_rn(v);
    }
}

// ---------------- edge dtype sniff ----------------
__global__ void k_detect(const unsigned int* __restrict__ ei32) {
    __shared__ int nz;
    if (threadIdx.x == 0) nz = 0;
    __syncthreads();
    for (int i = threadIdx.x; i < 4096; i += blockDim.x)
        if (ei32[2 * i + 1] != 0u) atomicOr(&nz, 1);
    __syncthreads();
    if (threadIdx.x == 0) g_is64 = nz ? 0 : 1;
}

// ---------------- GEMM1 (fp16) + fused alpha1 (proven R14 mainloop) ----------
__global__ void __launch_bounds__(256, 2) k_gemm1_mma(
        const float* __restrict__ asrc1, const float* __restrict__ adst1, int M) {
    extern __shared__ __align__(16) uint8_t sm[];
    int tid = threadIdx.x, lane = tid & 31, wid = tid >> 5;
    int warp_m = wid & 1, warp_n = wid >> 1;
    int rowBase = blockIdx.y << 7, colBase = blockIdx.x << 7;
    uint32_t uS = smem_u32(sm);

    int cRow = tid >> 1, cHalf = tid & 1;
    uint32_t aSz = (rowBase + cRow) < M ? 16u : 0u;
    const __half* Ap = g_xf  + (size_t)(rowBase + cRow) * NFEAT + cHalf * 8;
    const __half* Bp = g_wtf + (size_t)(colBase + cRow) * NFEAT + cHalf * 8;
    uint32_t cDst = (uint32_t)(cRow * ROWS_B + cHalf * 16);

    uint32_t aRel[4], bRel[2];
#pragma unroll
    for (int mt = 0; mt < 4; mt++)
        aRel[mt] = (uint32_t)((warp_m * 64 + mt * 16 + (lane & 15)) * ROWS_B
                              + (((lane >> 4) & 1) << 4));
    {
        int b_n = (lane & 7) | ((lane & 16) >> 1);
        int b_kb = (lane & 8) << 1;
#pragma unroll
        for (int bt = 0; bt < 2; bt++)
            bRel[bt] = (uint32_t)((warp_n * 32 + bt * 16 + b_n) * ROWS_B + b_kb);
    }

    float c[4][4][4];
#pragma unroll
    for (int i = 0; i < 4; i++)
#pragma unroll
        for (int j = 0; j < 4; j++)
#pragma unroll
            for (int q = 0; q < 4; q++) c[i][j][q] = 0.f;

    auto issue = [&](int kt, int buf) {
        uint32_t b = uS + (uint32_t)buf * STG_BYTES + cDst;
        CP16(b,         Ap + kt * 16, aSz);
        CP16(b + OFF_B, Bp + kt * 16, 16u);
    };

    issue(0, 0); CP_COMMIT();
    issue(1, 1); CP_COMMIT();
    issue(2, 2); CP_COMMIT();

    const int NT = NFEAT / 16;   // 32
    for (int kt = 0; kt < NT; kt++) {
        CP_WAIT2();
        __syncthreads();
        uint32_t base = uS + (uint32_t)(kt % NSTAGE) * STG_BYTES;

        uint32_t ah[4][4], bh[2][4];
#pragma unroll
        for (int mt = 0; mt < 4; mt++) ldsm4(base + aRel[mt], ah[mt]);
#pragma unroll
        for (int bt = 0; bt < 2; bt++) ldsm4(base + OFF_B + bRel[bt], bh[bt]);
#pragma unroll
        for (int mt = 0; mt < 4; mt++)
#pragma unroll
            for (int nt = 0; nt < 4; nt++) {
                int bi = nt >> 1, bj = (nt & 1) << 1;
                MMA_F16(c[mt][nt], ah[mt], bh[bi][bj], bh[bi][bj + 1]);
            }

        if (kt + 3 < NT) issue(kt + 3, (kt + 3) % NSTAGE);
        CP_COMMIT();
    }

    // epilogue: fp16 output + fused alpha partials
    int head = (colBase + warp_n * 32) >> 6;
    float a_s[8], a_d[8];
#pragma unroll
    for (int j = 0; j < 8; j++) {
        int col = colBase + warp_n * 32 + (j >> 1) * 8 + ((lane & 3) << 1) + (j & 1);
        a_s[j] = asrc1[col];
        a_d[j] = adst1[col];
    }
#pragma unroll
    for (int mt = 0; mt < 4; mt++) {
        int r0 = rowBase + warp_m * 64 + mt * 16 + (lane >> 2);
        float sa0 = 0.f, sd0 = 0.f, sa8 = 0.f, sd8 = 0.f;
#pragma unroll
        for (int nt = 0; nt < 4; nt++) {
            int col = colBase + warp_n * 32 + nt * 8 + ((lane & 3) << 1);
            sa0 += c[mt][nt][0] * a_s[nt * 2] + c[mt][nt][1] * a_s[nt * 2 + 1];
            sd0 += c[mt][nt][0] * a_d[nt * 2] + c[mt][nt][1] * a_d[nt * 2 + 1];
            sa8 += c[mt][nt][2] * a_s[nt * 2] + c[mt][nt][3] * a_s[nt * 2 + 1];
            sd8 += c[mt][nt][2] * a_d[nt * 2] + c[mt][nt][3] * a_d[nt * 2 + 1];
            if (r0 < M)
                *(__half2*)&g_h1h[(size_t)r0 * HHC + col] =
                    __floats2half2_rn(c[mt][nt][0], c[mt][nt][1]);
            if (r0 + 8 < M)
                *(__half2*)&g_h1h[(size_t)(r0 + 8) * HHC + col] =
                    __floats2half2_rn(c[mt][nt][2], c[mt][nt][3]);
        }
        sa0 += __shfl_xor_sync(0xffffffffu, sa0, 1); sa0 += __shfl_xor_sync(0xffffffffu, sa0, 2);
        sd0 += __shfl_xor_sync(0xffffffffu, sd0, 1); sd0 += __shfl_xor_sync(0xffffffffu, sd0, 2);
        sa8 += __shfl_xor_sync(0xffffffffu, sa8, 1); sa8 += __shfl_xor_sync(0xffffffffu, sa8, 2);
        sd8 += __shfl_xor_sync(0xffffffffu, sd8, 1); sd8 += __shfl_xor_sync(0xffffffffu, sd8, 2);
        if ((lane & 3) == 0) {
            if (r0 < M) {
                atomicAdd(&g_as1[r0 * NHEAD + head], sa0);
                atomicAdd(&g_ad1[r0 * NHEAD + head], sd0);
            }
            if (r0 + 8 < M) {
                atomicAdd(&g_as1[(r0 + 8) * NHEAD + head], sa8);
                atomicAdd(&g_ad1[(r0 + 8) * NHEAD + head], sd8);
            }
        }
    }
}

// ---------------- CSR build ----------------
__global__ void k_init0(int M) {
    int i = blockIdx.x * blockDim.x + threadIdx.x;
    if (i < M) { g_deg[i] = 0; g_fill[i] = 0; }
}
__global__ void k_convcount(const void* __restrict__ ei, int E, int EN) {
    int e = blockIdx.x * blockDim.x + threadIdx.x;
    if (e >= EN) return;
    int s, d;
    if (e < E) {
        if (g_is64) {
            const long long* p = (const long long*)ei;
            s = (int)p[e]; d = (int)p[(size_t)E + e];
        } else {
            const int* p = (const int*)ei;
            s = p[e]; d = p[E + e];
        }
    } else { s = e - E; d = e - E; }
    g_src[e] = s; g_dst[e] = d;
    atomicAdd(&g_deg[d], 1);
}
__global__ void k_scan(int M) {
    __shared__ int ss[1024];
    int t = threadIdx.x;
    int CH = (M + 1023) >> 10;
    int base = t * CH;
    int sum = 0;
    for (int i = 0; i < CH; i++) { int idx = base + i; if (idx < M) sum += g_deg[idx]; }
    ss[t] = sum; __syncthreads();
    for (int off = 1; off < 1024; off <<= 1) {
        int v = (t >= off) ? ss[t - off] : 0;
        __syncthreads();
        ss[t] += v;
        __syncthreads();
    }
    int off = (t == 0) ? 0 : ss[t - 1];
    for (int i = 0; i < CH; i++) {
        int idx = base + i;
        if (idx < M) { g_row[idx] = off; off += g_deg[idx]; }
    }
    if (t == 1023) g_row[M] = ss[1023];
}
__global__ void k_scatter(int EN) {
    int e = blockIdx.x * blockDim.x + threadIdx.x;
    if (e >= EN) return;
    int d = g_dst[e];
    int p = g_row[d] + atomicAdd(&g_fill[d], 1);
    g_csrc[p] = g_src[e];
}

// ---------------- layer1: fused softmax + aggregation (block per node) -------
__global__ void __launch_bounds__(128) k_aggr1(float* __restrict__ emb,
                                               const float* __restrict__ b1) {
    int n = blockIdx.x;
    int t = threadIdx.x;
    __shared__ float sden[32];
    __shared__ float sinv[8];
    __shared__ float sex[DEGCAP * NHEAD];   // 8KB
    int start = g_row[n], end = g_row[n + 1];
    int deg = end - start;
    bool small = deg <= DEGCAP;

    {
        int h = t & 7, slot = t >> 3;
        float ad = g_ad1[n * NHEAD + h];
        float den = 0.f;
        for (int p = start + slot; p < end; p += 16) {
            float v = g_as1[g_csrc[p] * NHEAD + h] + ad;
            v = v >= 0.f ? v : NEG * v;
            float ex = __expf(v);
            if (small) sex[(p - start) * NHEAD + h] = ex;
            else       g_ex1[(size_t)p * NHEAD + h] = ex;
            den += ex;
        }
        den += __shfl_xor_sync(0xffffffffu, den, 8);
        den += __shfl_xor_sync(0xffffffffu, den, 16);
        if ((t & 31) < 8) sden[(t >> 5) * 8 + h] = den;
    }
    __syncthreads();
    if (t < 8) sinv[t] = 1.f / (sden[t] + sden[8 + t] + sden[16 + t] + sden[24 + t]);
    __syncthreads();

    int h = t >> 4;
    float inv = sinv[h];
    float4 acc = make_float4(0.f, 0.f, 0.f, 0.f);
    const float* exp_src = small ? sex : nullptr;
    int p = start;
    for (; p + 3 < end; p += 4) {
        int s0 = g_csrc[p], s1 = g_csrc[p + 1], s2 = g_csrc[p + 2], s3 = g_csrc[p + 3];
        float a0, a1, a2, a3;
        if (small) {
            a0 = exp_src[(p - start) * NHEAD + h];
            a1 = exp_src[(p + 1 - start) * NHEAD + h];
            a2 = exp_src[(p + 2 - start) * NHEAD + h];
            a3 = exp_src[(p + 3 - start) * NHEAD + h];
        } else {
            a0 = g_ex1[(size_t)p * NHEAD + h];
            a1 = g_ex1[(size_t)(p + 1) * NHEAD + h];
            a2 = g_ex1[(size_t)(p + 2) * NHEAD + h];
            a3 = g_ex1[(size_t)(p + 3) * NHEAD + h];
        }
        uint2 r0 = *(const uint2*)(g_h1h + (size_t)s0 * HHC + (t << 2));
        uint2 r1 = *(const uint2*)(g_h1h + (size_t)s1 * HHC + (t << 2));
        uint2 r2 = *(const uint2*)(g_h1h + (size_t)s2 * HHC + (t << 2));
        uint2 r3 = *(const uint2*)(g_h1h + (size_t)s3 * HHC + (t << 2));
        float2 f0a = __half22float2(*(__half2*)&r0.x), f0b = __half22float2(*(__half2*)&r0.y);
        float2 f1a = __half22float2(*(__half2*)&r1.x), f1b = __half22float2(*(__half2*)&r1.y);
        float2 f2a = __half22float2(*(__half2*)&r2.x), f2b = __half22float2(*(__half2*)&r2.y);
        float2 f3a = __half22float2(*(__half2*)&r3.x), f3b = __half22float2(*(__half2*)&r3.y);
        acc.x += a0 * f0a.x + a1 * f1a.x + a2 * f2a.x + a3 * f3a.x;
        acc.y += a0 * f0a.y + a1 * f1a.y + a2 * f2a.y + a3 * f3a.y;
        acc.z += a0 * f0b.x + a1 * f1b.x + a2 * f2b.x + a3 * f3b.x;
        acc.w += a0 * f0b.y + a1 * f1b.y + a2 * f2b.y + a3 * f3b.y;
    }
    for (; p < end; p++) {
        int s = g_csrc[p];
        float a = small ? exp_src[(p - start) * NHEAD + h] : g_ex1[(size_t)p * NHEAD + h];
        uint2 raw = *(const uint2*)(g_h1h + (size_t)s * HHC + (t << 2));
        float2 f01 = __half22float2(*(__half2*)&raw.x);
        float2 f23 = __half22float2(*(__half2*)&raw.y);
        acc.x += a * f01.x; acc.y += a * f01.y;
        acc.z += a * f23.x; acc.w += a * f23.y;
    }
    acc.x *= inv; acc.y *= inv; acc.z *= inv; acc.w *= inv;
    float4 bv = ((const float4*)b1)[t];
    acc.x += bv.x; acc.y += bv.y; acc.z += bv.z; acc.w += bv.w;
    ((float4*)(emb + (size_t)n * HHC))[t] = acc;
    float ex = acc.x > 0.f ? acc.x : expm1f(acc.x);
    float ey = acc.y > 0.f ? acc.y : expm1f(acc.y);
    float ez = acc.z > 0.f ? acc.z : expm1f(acc.z);
    float ew = acc.w > 0.f ? acc.w : expm1f(acc.w);
    uint2 out;
    *(__half2*)&out.x = __floats2half2_rn(ex, ey);
    *(__half2*)&out.y = __floats2half2_rn(ez, ew);
    *(uint2*)(g_hactH + (size_t)n * HHC + (t << 2)) = out;
}

// ---------------- GEMM2 + alpha2 (fused; 64 nodes/block) ----------------
__global__ void k_gemm2(const float* __restrict__ W2, const float* __restrict__ asrc,
                        const float* __restrict__ adst, int M) {
    __shared__ float Ws[NFEAT * NCLS];
    for (int i = threadIdx.x; i < NFEAT * NCLS; i += 256) Ws[i] = W2[i];
    __syncthreads();
    int c = threadIdx.x & 15;
    int r = threadIdx.x >> 4;          // 0..15
    float as_c = asrc[c], ad_c = adst[c];
#pragma unroll
    for (int g = 0; g < 4; g++) {
        int n = blockIdx.x * 64 + g * 16 + r;
        if (n >= M) return;
        const uint4* hr8 = (const uint4*)(g_hactH + (size_t)n * HHC);
        float acc = 0.f;
#pragma unroll 4
        for (int k8 = 0; k8 < NFEAT / 8; k8++) {
            uint4 raw = hr8[k8];
            float2 f0 = __half22float2(*(__half2*)&raw.x);
            float2 f1 = __half22float2(*(__half2*)&raw.y);
            float2 f2 = __half22float2(*(__half2*)&raw.z);
            float2 f3 = __half22float2(*(__half2*)&raw.w);
            int k = k8 * 8;
            acc += f0.x * Ws[(k + 0) * NCLS + c] + f0.y * Ws[(k + 1) * NCLS + c];
            acc += f1.x * Ws[(k + 2) * NCLS + c] + f1.y * Ws[(k + 3) * NCLS + c];
            acc += f2.x * Ws[(k + 4) * NCLS + c] + f2.y * Ws[(k + 5) * NCLS + c];
            acc += f3.x * Ws[(k + 6) * NCLS + c] + f3.y * Ws[(k + 7) * NCLS + c];
        }
        g_h2[(size_t)n * NCLS + c] = acc;
        float sa = acc * as_c, sd = acc * ad_c;
#pragma unroll
        for (int o = 8; o; o >>= 1) {
            sa += __shfl_xor_sync(0xffffffffu, sa, o);
            sd += __shfl_xor_sync(0xffffffffu, sd, o);
        }
        if (c == 0) { g_as2[n] = sa; g_ad2[n] = sd; }
    }
}

// ---------------- layer2: fused softmax + aggregation (warp per node) --------
__global__ void k_l2(float* __restrict__ logits, const float* __restrict__ b2, int M) {
    int n = (blockIdx.x * blockDim.x + threadIdx.x) >> 5;
    int lane = threadIdx.x & 31;
    if (n >= M) return;
    int start = g_row[n], end = g_row[n + 1];
    float ad = g_ad2[n];
    float den = 0.f;
    for (int p = start + lane; p < end; p += 32) {
        float v = g_as2[g_csrc[p]] + ad;
        v = v >= 0.f ? v : NEG * v;
        float ex = __expf(v);
        g_ex2[p] = ex;
        den += ex;
    }
#pragma unroll
    for (int o = 16; o; o >>= 1) den += __shfl_xor_sync(0xffffffffu, den, o);
    float inv = 1.f / den;
    __threadfence_block();
    __syncwarp();
    int c = lane & 15, half = lane >> 4;
    float acc = 0.f;
    for (int p = start + half; p < end; p += 2)
        acc += g_ex2[p] * g_h2[(size_t)g_csrc[p] * NCLS + c];
    acc += __shfl_xor_sync(0xffffffffu, acc, 16);
    if (lane < 16) logits[(size_t)n * NCLS + lane] = acc * inv + b2[lane];
}

// ---------------- launch ----------------
extern "C" void kernel_launch(void* const* d_in, const int* in_sizes, int n_in,
                              void* d_out, int out_size) {
    const float* x     = (const float*)d_in[0];
    const void*  ei    = d_in[1];
    const float* w1    = (const float*)d_in[2];
    const float* asrc1 = (const float*)d_in[3];
    const float* adst1 = (const float*)d_in[4];
    const float* b1    = (const float*)d_in[5];
    const float* w2    = (const float*)d_in[6];
    const float* asrc2 = (const float*)d_in[7];
    const float* adst2 = (const float*)d_in[8];
    const float* b2    = (const float*)d_in[9];

    const int M  = in_sizes[0] / NFEAT;     // 50000
    const int E  = in_sizes[1] / 2;         // 800000
    const int EN = E + M;                   // 850000

    float* logits = (float*)d_out;
    float* emb    = logits + (size_t)M * NCLS;

    static cudaStream_t s2 = nullptr;
    static cudaEvent_t evFork = nullptr, evJoin = nullptr;
    if (!s2) {
        cudaStreamCreateWithFlags(&s2, cudaStreamNonBlocking);
        cudaEventCreateWithFlags(&evFork, cudaEventDisableTiming);
        cudaEventCreateWithFlags(&evJoin, cudaEventDisableTiming);
    }

    cudaFuncSetAttribute(k_gemm1_mma, cudaFuncAttributeMaxDynamicSharedMemorySize, DSMEM_G1);

    cudaEventRecord(evFork, 0);
    cudaStreamWaitEvent(s2, evFork, 0);

    size_t n4 = (size_t)M * NFEAT / 4;
    k_cvt_x<<<(unsigned)((n4 + 255) / 256), 256>>>(x, n4, M);         // 1 main (+zero)
    {
        dim3 g(16, 16), b(32, 8);
        k_cvt_wt<<<g, b>>>(w1);                                        // 2 main
    }
    {
        dim3 grid(HHC / 128, (M + 127) / 128);
        k_gemm1_mma<<<grid, 256, DSMEM_G1>>>(asrc1, adst1, M);         // 3 main (profiled)
    }
    // side stream: CSR build, concurrent with gemm1
    k_detect<<<1, 256, 0, s2>>>((const unsigned int*)ei);
    k_init0<<<(M + 255) / 256, 256, 0, s2>>>(M);
    k_convcount<<<(EN + 255) / 256, 256, 0, s2>>>(ei, E, EN);
    k_scan<<<1, 1024, 0, s2>>>(M);
    k_scatter<<<(EN + 255) / 256, 256, 0, s2>>>(EN);
    cudaEventRecord(evJoin, s2);

    cudaStreamWaitEvent(0, evJoin, 0);
    k_aggr1<<<M, 128>>>(emb, b1);

    k_gemm2<<<(M + 63) / 64, 256>>>(w2, asrc2, adst2, M);
    k_l2<<<((M * 32) + 255) / 256, 256>>>(logits, b2, M);
}

// round 17
// speedup vs baseline: 1.0232x; 1.0232x over previous
#include <cuda_runtime.h>
#include <cuda_fp16.h>
#include <math.h>
#include <stdint.h>

#define NNODES 50000
#define NFEAT  512
#define HHC    512
#define NHEAD  8
#define NCLS   16
#define NEG    0.2f
#define MAXEN  850000
#define DEGCAP 256

// GEMM1 smem staging: 2 regions (A, B) x 128 rows x 48B pitch per k-tile stage
#define ROWS_B    48
#define REGION    (128 * ROWS_B)     // 6144
#define OFF_B     REGION
#define STG_BYTES (2 * REGION)       // 12288 per stage (one k-tile)
#define NPAIR     3                  // 3 pairs = 6 stages
#define PAIR_BYTES (2 * STG_BYTES)   // 24576
#define DSMEM_G1  (NPAIR * PAIR_BYTES)  // 73728

// ---------------- scratch ----------------
__device__ __half g_h1h  [(size_t)NNODES * HHC];  // layer1 features, fp16
__device__ __half g_hactH[(size_t)NNODES * HHC];  // elu(emb), fp16
__device__ float g_h2  [(size_t)NNODES * NCLS];
__device__ __half g_xf [(size_t)NNODES * NFEAT];  // x, fp16
__device__ __half g_wtf[NFEAT * HHC];             // W1^T, fp16 [n][k]
__device__ float g_as1[NNODES * NHEAD];
__device__ float g_ad1[NNODES * NHEAD];
__device__ float g_as2[NNODES];
__device__ float g_ad2[NNODES];
__device__ float g_ex1[(size_t)MAXEN * NHEAD];  // fallback for deg > DEGCAP
__device__ float g_ex2[MAXEN];
__device__ int   g_src[MAXEN];
__device__ int   g_dst[MAXEN];
__device__ int   g_csrc[MAXEN];
__device__ int   g_row[NNODES + 1];
__device__ int   g_deg[NNODES];
__device__ int   g_fill[NNODES];
__device__ int   g_is64;

// ---------------- helpers ----------------
__device__ __forceinline__ uint32_t smem_u32(const void* p) {
    uint32_t a;
    asm("{ .reg .u64 t; cvta.to.shared.u64 t, %1; cvt.u32.u64 %0, t; }" : "=r"(a) : "l"(p));
    return a;
}
__device__ __forceinline__ void ldsm4(uint32_t addr, uint32_t* r) {
    asm volatile("ldmatrix.sync.aligned.m8n8.x4.shared.b16 {%0,%1,%2,%3}, [%4];"
                 : "=r"(r[0]), "=r"(r[1]), "=r"(r[2]), "=r"(r[3]) : "r"(addr));
}
#define MMA_F16(c, a, b0, b1) \
    asm volatile("mma.sync.aligned.m16n8k16.row.col.f32.f16.f16.f32 " \
        "{%0,%1,%2,%3}, {%4,%5,%6,%7}, {%8,%9}, {%0,%1,%2,%3};" \
        : "+f"((c)[0]), "+f"((c)[1]), "+f"((c)[2]), "+f"((c)[3]) \
        : "r"((a)[0]), "r"((a)[1]), "r"((a)[2]), "r"((a)[3]), "r"(b0), "r"(b1))

#define CP16(dst, src, sz) \
    asm volatile("cp.async.cg.shared.global [%0], [%1], 16, %2;" \
                 :: "r"(dst), "l"(src), "r"(sz) : "memory")
#define CP_COMMIT() asm volatile("cp.async.commit_group;" ::: "memory")
#define CP_WAIT1()  asm volatile("cp.async.wait_group 1;" ::: "memory")

// ---------------- convert x -> fp16 (+ zero alpha accumulators) --------------
__global__ void k_cvt_x(const float* __restrict__ x, size_t n4, int M) {
    size_t i = (size_t)blockIdx.x * blockDim.x + threadIdx.x;
    if (i < (size_t)M * NHEAD) { g_as1[i] = 0.f; g_ad1[i] = 0.f; }
    if (i >= n4) return;
    float4 v = ((const float4*)x)[i];
    uint2 out;
    *(__half2*)&out.x = __floats2half2_rn(v.x, v.y);
    *(__half2*)&out.y = __floats2half2_rn(v.z, v.w);
    ((uint2*)g_xf)[i] = out;
}

// ---------------- W1 transpose + convert ----------------
__global__ void k_cvt_wt(const float* __restrict__ w1) {
    __shared__ float t[32][33];
    int bx = blockIdx.x * 32, by = blockIdx.y * 32;
#pragma unroll
    for (int j = 0; j < 32; j += 8)
        t[threadIdx.y + j][threadIdx.x] = w1[(size_t)(by + threadIdx.y + j) * HHC + bx + threadIdx.x];
    __syncthreads();
#pragma unroll
    for (int j = 0; j < 32; j += 8) {
        float v = t[threadIdx.x][threadIdx.y + j];
        g_wtf[(size_t)(bx + threadIdx.y + j) * NFEAT + by + threadIdx.x] = __float2half_rn(v);
    }
}

// ---------------- edge dtype sniff ----------------
__global__ void k_detect(const unsigned int* __restrict__ ei32) {
    __shared__ int nz;
    if (threadIdx.x == 0) nz = 0;
    __syncthreads();
    for (int i = threadIdx.x; i < 4096; i += blockDim.x)
        if (ei32[2 * i + 1] != 0u) atomicOr(&nz, 1);
    __syncthreads();
    if (threadIdx.x == 0) g_is64 = nz ? 0 : 1;
}

// ---------------- GEMM1 (fp16) + fused alpha1; 3-pair pipeline ---------------
// Iteration pi: waits+syncs once, consumes 2 k-tiles from pair pi%3,
// issues pair (pi+2)%3 == (pi-1)%3 (consumed LAST iteration; safe after sync).
__global__ void __launch_bounds__(256, 2) k_gemm1_mma(
        const float* __restrict__ asrc1, const float* __restrict__ adst1, int M) {
    extern __shared__ __align__(16) uint8_t sm[];
    int tid = threadIdx.x, lane = tid & 31, wid = tid >> 5;
    int warp_m = wid & 1, warp_n = wid >> 1;
    int rowBase = blockIdx.y << 7, colBase = blockIdx.x << 7;
    uint32_t uS = smem_u32(sm);

    int cRow = tid >> 1, cHalf = tid & 1;
    uint32_t aSz = (rowBase + cRow) < M ? 16u : 0u;
    const __half* Ap = g_xf  + (size_t)(rowBase + cRow) * NFEAT + cHalf * 8;
    const __half* Bp = g_wtf + (size_t)(colBase + cRow) * NFEAT + cHalf * 8;
    uint32_t cDst = (uint32_t)(cRow * ROWS_B + cHalf * 16);

    uint32_t aRel[4], bRel[2];
#pragma unroll
    for (int mt = 0; mt < 4; mt++)
        aRel[mt] = (uint32_t)((warp_m * 64 + mt * 16 + (lane & 15)) * ROWS_B
                              + (((lane >> 4) & 1) << 4));
    {
        int b_n = (lane & 7) | ((lane & 16) >> 1);
        int b_kb = (lane & 8) << 1;
#pragma unroll
        for (int bt = 0; bt < 2; bt++)
            bRel[bt] = (uint32_t)((warp_n * 32 + bt * 16 + b_n) * ROWS_B + b_kb);
    }

    float c[4][4][4];
#pragma unroll
    for (int i = 0; i < 4; i++)
#pragma unroll
        for (int j = 0; j < 4; j++)
#pragma unroll
            for (int q = 0; q < 4; q++) c[i][j][q] = 0.f;

    auto issue = [&](int kt, uint32_t stgBase) {   // one k-tile into one stage
        uint32_t b = stgBase + cDst;
        CP16(b,         Ap + kt * 16, aSz);
        CP16(b + OFF_B, Bp + kt * 16, 16u);
    };
    auto issue_pair = [&](int pairIdx, int ktBase) {
        uint32_t pb = uS + (uint32_t)pairIdx * PAIR_BYTES;
        issue(ktBase, pb);
        issue(ktBase + 1, pb + STG_BYTES);
        CP_COMMIT();
    };
    auto tile = [&](uint32_t base) {
        uint32_t ah[4][4], bh[2][4];
#pragma unroll
        for (int mt = 0; mt < 4; mt++) ldsm4(base + aRel[mt], ah[mt]);
#pragma unroll
        for (int bt = 0; bt < 2; bt++) ldsm4(base + OFF_B + bRel[bt], bh[bt]);
#pragma unroll
        for (int mt = 0; mt < 4; mt++)
#pragma unroll
            for (int nt = 0; nt < 4; nt++) {
                int bi = nt >> 1, bj = (nt & 1) << 1;
                MMA_F16(c[mt][nt], ah[mt], bh[bi][bj], bh[bi][bj + 1]);
            }
    };

    issue_pair(0, 0);
    issue_pair(1, 2);

    const int NP = NFEAT / 32;   // 16
    for (int pi = 0; pi < NP; pi++) {
        CP_WAIT1();
        __syncthreads();
        uint32_t pb = uS + (uint32_t)(pi % NPAIR) * PAIR_BYTES;
        tile(pb);
        tile(pb + STG_BYTES);
        if (pi + 2 < NP)
            issue_pair((pi + 2) % NPAIR, (pi + 2) * 2);
    }

    // epilogue: fp16 output + fused alpha partials
    int head = (colBase + warp_n * 32) >> 6;
    float a_s[8], a_d[8];
#pragma unroll
    for (int j = 0; j < 8; j++) {
        int col = colBase + warp_n * 32 + (j >> 1) * 8 + ((lane & 3) << 1) + (j & 1);
        a_s[j] = asrc1[col];
        a_d[j] = adst1[col];
    }
#pragma unroll
    for (int mt = 0; mt < 4; mt++) {
        int r0 = rowBase + warp_m * 64 + mt * 16 + (lane >> 2);
        float sa0 = 0.f, sd0 = 0.f, sa8 = 0.f, sd8 = 0.f;
#pragma unroll
        for (int nt = 0; nt < 4; nt++) {
            int col = colBase + warp_n * 32 + nt * 8 + ((lane & 3) << 1);
            sa0 += c[mt][nt][0] * a_s[nt * 2] + c[mt][nt][1] * a_s[nt * 2 + 1];
            sd0 += c[mt][nt][0] * a_d[nt * 2] + c[mt][nt][1] * a_d[nt * 2 + 1];
            sa8 += c[mt][nt][2] * a_s[nt * 2] + c[mt][nt][3] * a_s[nt * 2 + 1];
            sd8 += c[mt][nt][2] * a_d[nt * 2] + c[mt][nt][3] * a_d[nt * 2 + 1];
            if (r0 < M)
                *(__half2*)&g_h1h[(size_t)r0 * HHC + col] =
                    __floats2half2_rn(c[mt][nt][0], c[mt][nt][1]);
            if (r0 + 8 < M)
                *(__half2*)&g_h1h[(size_t)(r0 + 8) * HHC + col] =
                    __floats2half2_rn(c[mt][nt][2], c[mt][nt][3]);
        }
        sa0 += __shfl_xor_sync(0xffffffffu, sa0, 1); sa0 += __shfl_xor_sync(0xffffffffu, sa0, 2);
        sd0 += __shfl_xor_sync(0xffffffffu, sd0, 1); sd0 += __shfl_xor_sync(0xffffffffu, sd0, 2);
        sa8 += __shfl_xor_sync(0xffffffffu, sa8, 1); sa8 += __shfl_xor_sync(0xffffffffu, sa8, 2);
        sd8 += __shfl_xor_sync(0xffffffffu, sd8, 1); sd8 += __shfl_xor_sync(0xffffffffu, sd8, 2);
        if ((lane & 3) == 0) {
            if (r0 < M) {
                atomicAdd(&g_as1[r0 * NHEAD + head], sa0);
                atomicAdd(&g_ad1[r0 * NHEAD + head], sd0);
            }
            if (r0 + 8 < M) {
                atomicAdd(&g_as1[(r0 + 8) * NHEAD + head], sa8);
                atomicAdd(&g_ad1[(r0 + 8) * NHEAD + head], sd8);
            }
        }
    }
}

// ---------------- CSR build ----------------
__global__ void k_init0(int M) {
    int i = blockIdx.x * blockDim.x + threadIdx.x;
    if (i < M) { g_deg[i] = 0; g_fill[i] = 0; }
}
__global__ void k_convcount(const void* __restrict__ ei, int E, int EN) {
    int e = blockIdx.x * blockDim.x + threadIdx.x;
    if (e >= EN) return;
    int s, d;
    if (e < E) {
        if (g_is64) {
            const long long* p = (const long long*)ei;
            s = (int)p[e]; d = (int)p[(size_t)E + e];
        } else {
            const int* p = (const int*)ei;
            s = p[e]; d = p[E + e];
        }
    } else { s = e - E; d = e - E; }
    g_src[e] = s; g_dst[e] = d;
    atomicAdd(&g_deg[d], 1);
}
__global__ void k_scan(int M) {
    __shared__ int ss[1024];
    int t = threadIdx.x;
    int CH = (M + 1023) >> 10;
    int base = t * CH;
    int sum = 0;
    for (int i = 0; i < CH; i++) { int idx = base + i; if (idx < M) sum += g_deg[idx]; }
    ss[t] = sum; __syncthreads();
    for (int off = 1; off < 1024; off <<= 1) {
        int v = (t >= off) ? ss[t - off] : 0;
        __syncthreads();
        ss[t] += v;
        __syncthreads();
    }
    int off = (t == 0) ? 0 : ss[t - 1];
    for (int i = 0; i < CH; i++) {
        int idx = base + i;
        if (idx < M) { g_row[idx] = off; off += g_deg[idx]; }
    }
    if (t == 1023) g_row[M] = ss[1023];
}
__global__ void k_scatter(int EN) {
    int e = blockIdx.x * blockDim.x + threadIdx.x;
    if (e >= EN) return;
    int d = g_dst[e];
    int p = g_row[d] + atomicAdd(&g_fill[d], 1);
    g_csrc[p] = g_src[e];
}

// ---------------- layer1: fused softmax + aggregation (block per node) -------
__global__ void __launch_bounds__(128) k_aggr1(float* __restrict__ emb,
                                               const float* __restrict__ b1) {
    int n = blockIdx.x;
    int t = threadIdx.x;
    __shared__ float sden[32];
    __shared__ float sinv[8];
    __shared__ float sex[DEGCAP * NHEAD];   // 8KB
    int start = g_row[n], end = g_row[n + 1];
    int deg = end - start;
    bool small = deg <= DEGCAP;

    {
        int h = t & 7, slot = t >> 3;
        float ad = g_ad1[n * NHEAD + h];
        float den = 0.f;
        for (int p = start + slot; p < end; p += 16) {
            float v = g_as1[g_csrc[p] * NHEAD + h] + ad;
            v = v >= 0.f ? v : NEG * v;
            float ex = __expf(v);
            if (small) sex[(p - start) * NHEAD + h] = ex;
            else       g_ex1[(size_t)p * NHEAD + h] = ex;
            den += ex;
        }
        den += __shfl_xor_sync(0xffffffffu, den, 8);
        den += __shfl_xor_sync(0xffffffffu, den, 16);
        if ((t & 31) < 8) sden[(t >> 5) * 8 + h] = den;
    }
    __syncthreads();
    if (t < 8) sinv[t] = 1.f / (sden[t] + sden[8 + t] + sden[16 + t] + sden[24 + t]);
    __syncthreads();

    int h = t >> 4;
    float inv = sinv[h];
    float4 acc = make_float4(0.f, 0.f, 0.f, 0.f);
    const float* exp_src = small ? sex : nullptr;
    int p = start;
    for (; p + 3 < end; p += 4) {
        int s0 = g_csrc[p], s1 = g_csrc[p + 1], s2 = g_csrc[p + 2], s3 = g_csrc[p + 3];
        float a0, a1, a2, a3;
        if (small) {
            a0 = exp_src[(p - start) * NHEAD + h];
            a1 = exp_src[(p + 1 - start) * NHEAD + h];
            a2 = exp_src[(p + 2 - start) * NHEAD + h];
            a3 = exp_src[(p + 3 - start) * NHEAD + h];
        } else {
            a0 = g_ex1[(size_t)p * NHEAD + h];
            a1 = g_ex1[(size_t)(p + 1) * NHEAD + h];
            a2 = g_ex1[(size_t)(p + 2) * NHEAD + h];
            a3 = g_ex1[(size_t)(p + 3) * NHEAD + h];
        }
        uint2 r0 = *(const uint2*)(g_h1h + (size_t)s0 * HHC + (t << 2));
        uint2 r1 = *(const uint2*)(g_h1h + (size_t)s1 * HHC + (t << 2));
        uint2 r2 = *(const uint2*)(g_h1h + (size_t)s2 * HHC + (t << 2));
        uint2 r3 = *(const uint2*)(g_h1h + (size_t)s3 * HHC + (t << 2));
        float2 f0a = __half22float2(*(__half2*)&r0.x), f0b = __half22float2(*(__half2*)&r0.y);
        float2 f1a = __half22float2(*(__half2*)&r1.x), f1b = __half22float2(*(__half2*)&r1.y);
        float2 f2a = __half22float2(*(__half2*)&r2.x), f2b = __half22float2(*(__half2*)&r2.y);
        float2 f3a = __half22float2(*(__half2*)&r3.x), f3b = __half22float2(*(__half2*)&r3.y);
        acc.x += a0 * f0a.x + a1 * f1a.x + a2 * f2a.x + a3 * f3a.x;
        acc.y += a0 * f0a.y + a1 * f1a.y + a2 * f2a.y + a3 * f3a.y;
        acc.z += a0 * f0b.x + a1 * f1b.x + a2 * f2b.x + a3 * f3b.x;
        acc.w += a0 * f0b.y + a1 * f1b.y + a2 * f2b.y + a3 * f3b.y;
    }
    for (; p < end; p++) {
        int s = g_csrc[p];
        float a = small ? exp_src[(p - start) * NHEAD + h] : g_ex1[(size_t)p * NHEAD + h];
        uint2 raw = *(const uint2*)(g_h1h + (size_t)s * HHC + (t << 2));
        float2 f01 = __half22float2(*(__half2*)&raw.x);
        float2 f23 = __half22float2(*(__half2*)&raw.y);
        acc.x += a * f01.x; acc.y += a * f01.y;
        acc.z += a * f23.x; acc.w += a * f23.y;
    }
    acc.x *= inv; acc.y *= inv; acc.z *= inv; acc.w *= inv;
    float4 bv = ((const float4*)b1)[t];
    acc.x += bv.x; acc.y += bv.y; acc.z += bv.z; acc.w += bv.w;
    ((float4*)(emb + (size_t)n * HHC))[t] = acc;
    float ex = acc.x > 0.f ? acc.x : expm1f(acc.x);
    float ey = acc.y > 0.f ? acc.y : expm1f(acc.y);
    float ez = acc.z > 0.f ? acc.z : expm1f(acc.z);
    float ew = acc.w > 0.f ? acc.w : expm1f(acc.w);
    uint2 out;
    *(__half2*)&out.x = __floats2half2_rn(ex, ey);
    *(__half2*)&out.y = __floats2half2_rn(ez, ew);
    *(uint2*)(g_hactH + (size_t)n * HHC + (t << 2)) = out;
}

// ---------------- GEMM2 + alpha2 (fused, fp16 hact; 16 nodes/block) ----------
__global__ void k_gemm2(const float* __restrict__ W2, const float* __restrict__ asrc,
                        const float* __restrict__ adst, int M) {
    __shared__ float Ws[NFEAT * NCLS];
    for (int i = threadIdx.x; i < NFEAT * NCLS; i += 256) Ws[i] = W2[i];
    __syncthreads();
    int c = threadIdx.x & 15;
    int n = blockIdx.x * 16 + (threadIdx.x >> 4);
    if (n >= M) return;
    const uint4* hr8 = (const uint4*)(g_hactH + (size_t)n * HHC);
    float acc = 0.f;
#pragma unroll 4
    for (int k8 = 0; k8 < NFEAT / 8; k8++) {
        uint4 raw = hr8[k8];
        float2 f0 = __half22float2(*(__half2*)&raw.x);
        float2 f1 = __half22float2(*(__half2*)&raw.y);
        float2 f2 = __half22float2(*(__half2*)&raw.z);
        float2 f3 = __half22float2(*(__half2*)&raw.w);
        int k = k8 * 8;
        acc += f0.x * Ws[(k + 0) * NCLS + c] + f0.y * Ws[(k + 1) * NCLS + c];
        acc += f1.x * Ws[(k + 2) * NCLS + c] + f1.y * Ws[(k + 3) * NCLS + c];
        acc += f2.x * Ws[(k + 4) * NCLS + c] + f2.y * Ws[(k + 5) * NCLS + c];
        acc += f3.x * Ws[(k + 6) * NCLS + c] + f3.y * Ws[(k + 7) * NCLS + c];
    }
    g_h2[(size_t)n * NCLS + c] = acc;
    float sa = acc * asrc[c], sd = acc * adst[c];
#pragma unroll
    for (int o = 8; o; o >>= 1) {
        sa += __shfl_xor_sync(0xffffffffu, sa, o);
        sd += __shfl_xor_sync(0xffffffffu, sd, o);
    }
    if (c == 0) { g_as2[n] = sa; g_ad2[n] = sd; }
}

// ---------------- layer2: fused softmax + aggregation (warp per node) --------
__global__ void k_l2(float* __restrict__ logits, const float* __restrict__ b2, int M) {
    int n = (blockIdx.x * blockDim.x + threadIdx.x) >> 5;
    int lane = threadIdx.x & 31;
    if (n >= M) return;
    int start = g_row[n], end = g_row[n + 1];
    float ad = g_ad2[n];
    float den = 0.f;
    for (int p = start + lane; p < end; p += 32) {
        float v = g_as2[g_csrc[p]] + ad;
        v = v >= 0.f ? v : NEG * v;
        float ex = __expf(v);
        g_ex2[p] = ex;
        den += ex;
    }
#pragma unroll
    for (int o = 16; o; o >>= 1) den += __shfl_xor_sync(0xffffffffu, den, o);
    float inv = 1.f / den;
    __threadfence_block();
    __syncwarp();
    int c = lane & 15, half = lane >> 4;
    float acc = 0.f;
    for (int p = start + half; p < end; p += 2)
        acc += g_ex2[p] * g_h2[(size_t)g_csrc[p] * NCLS + c];
    acc += __shfl_xor_sync(0xffffffffu, acc, 16);
    if (lane < 16) logits[(size_t)n * NCLS + lane] = acc * inv + b2[lane];
}

// ---------------- launch ----------------
extern "C" void kernel_launch(void* const* d_in, const int* in_sizes, int n_in,
                              void* d_out, int out_size) {
    const float* x     = (const float*)d_in[0];
    const void*  ei    = d_in[1];
    const float* w1    = (const float*)d_in[2];
    const float* asrc1 = (const float*)d_in[3];
    const float* adst1 = (const float*)d_in[4];
    const float* b1    = (const float*)d_in[5];
    const float* w2    = (const float*)d_in[6];
    const float* asrc2 = (const float*)d_in[7];
    const float* adst2 = (const float*)d_in[8];
    const float* b2    = (const float*)d_in[9];

    const int M  = in_sizes[0] / NFEAT;     // 50000
    const int E  = in_sizes[1] / 2;         // 800000
    const int EN = E + M;                   // 850000

    float* logits = (float*)d_out;
    float* emb    = logits + (size_t)M * NCLS;

    static cudaStream_t s2 = nullptr;
    static cudaEvent_t evFork = nullptr, evJoin = nullptr;
    if (!s2) {
        cudaStreamCreateWithFlags(&s2, cudaStreamNonBlocking);
        cudaEventCreateWithFlags(&evFork, cudaEventDisableTiming);
        cudaEventCreateWithFlags(&evJoin, cudaEventDisableTiming);
    }

    cudaFuncSetAttribute(k_gemm1_mma, cudaFuncAttributeMaxDynamicSharedMemorySize, DSMEM_G1);

    cudaEventRecord(evFork, 0);
    cudaStreamWaitEvent(s2, evFork, 0);

    size_t n4 = (size_t)M * NFEAT / 4;
    k_cvt_x<<<(unsigned)((n4 + 255) / 256), 256>>>(x, n4, M);         // 1 main (+zero)
    {
        dim3 g(16, 16), b(32, 8);
        k_cvt_wt<<<g, b>>>(w1);                                        // 2 main
    }
    {
        dim3 grid(HHC / 128, (M + 127) / 128);
        k_gemm1_mma<<<grid, 256, DSMEM_G1>>>(asrc1, adst1, M);         // 3 main
    }
    // side stream: CSR build, concurrent with gemm1
    k_detect<<<1, 256, 0, s2>>>((const unsigned int*)ei);
    k_init0<<<(M + 255) / 256, 256, 0, s2>>>(M);
    k_convcount<<<(EN + 255) / 256, 256, 0, s2>>>(ei, E, EN);
    k_scan<<<1, 1024, 0, s2>>>(M);
    k_scatter<<<(EN + 255) / 256, 256, 0, s2>>>(EN);
    cudaEventRecord(evJoin, s2);

    cudaStreamWaitEvent(0, evJoin, 0);
    k_aggr1<<<M, 128>>>(emb, b1);

    k_gemm2<<<(M + 15) / 16, 256>>>(w2, asrc2, adst2, M);
    k_l2<<<((M * 32) + 255) / 256, 256>>>(logits, b2, M);
}